// round 17
// baseline (speedup 1.0000x reference)
#include <cuda_runtime.h>
#include <math.h>

#define BATCH 16
#define SEQ 1024
#define IN_DIM 310
#define E 64
#define NH 8
#define HD 8
#define ROWS (BATCH*SEQ)          // 16384
#define WIN 5
#define NKEYS 342                 // #{j < 1024 : j%3==0}
#define SCALE 0.35355339059327373f  // 1/sqrt(8)

typedef unsigned long long ull;

// ---------------- f32x2 packed helpers ----------------
__device__ __forceinline__ ull pk2(float lo, float hi) {
    ull r; asm("mov.b64 %0,{%1,%2};" : "=l"(r) : "f"(lo), "f"(hi)); return r;
}
__device__ __forceinline__ void upk2(ull v, float& lo, float& hi) {
    asm("mov.b64 {%0,%1},%2;" : "=f"(lo), "=f"(hi) : "l"(v));
}
__device__ __forceinline__ ull ffma2(ull a, ull b, ull c) {
    ull d; asm("fma.rn.f32x2 %0,%1,%2,%3;" : "=l"(d) : "l"(a), "l"(b), "l"(c)); return d;
}
__device__ __forceinline__ ull fmul2(ull a, ull b) {
    ull d; asm("mul.rn.f32x2 %0,%1,%2;" : "=l"(d) : "l"(a), "l"(b)); return d;
}

// ---------------- scratch ----------------
__device__ float g_xp[ROWS*E];
__device__ float g_q[2][BATCH*NH*SEQ*HD];
__device__ float g_k[2][BATCH*NH*SEQ*HD];
__device__ float g_v[2][BATCH*NH*SEQ*HD];
__device__ float g_o[2][ROWS*E];
__device__ float g_M[2][E*E];     // M_g = fw_g @ out_w_g  (64x64)
__device__ float g_cb[E];         // combined bias
__device__ float g_N[2][32*E];    // N_g = w1 @ M_g  (32x64)
__device__ float g_cb1[32];       // w1 @ cb + b1
__device__ float g_part[2][BATCH][32][64];  // pooled partials (32 chunks of 32 rows)
__device__ float g_esum[BATCH][32];         // exp-sum partials

// ======== split GEMM: 64x64 tile, TWO 128-thread groups, microtile 8x4 each ========
struct HalfSmem {
    float As[16][68];
    float Ws[16][68];
};
struct SplitSmem {
    HalfSmem h[2];
    float part[64][68];
};

__device__ __forceinline__ void gemm64_grp(
    HalfSmem& sm,
    const float* __restrict__ A, int lda, int row0,
    const float* __restrict__ W, int ldw,
    int kb, int ke, int nchunk,
    ull (&acc)[4][4], int t)
{
    int tc = t & 15, tr = t >> 4;   // tr 0..7
    for (int ci = 0; ci < nchunk; ci++) {
        int k0 = kb + ci * 16;
        #pragma unroll
        for (int p = 0; p < 8; p++) {      // A: 64x16
            int i = t + p * 128;
            int kk = i & 15, r = i >> 4;
            int k = k0 + kk;
            sm.As[kk][r] = (k < ke) ? A[(size_t)(row0 + r) * lda + k] : 0.f;
        }
        #pragma unroll
        for (int p = 0; p < 8; p++) {      // W: 64x16
            int i = t + p * 128;
            int kk = i & 15, c = i >> 4;
            int k = k0 + kk;
            sm.Ws[kk][c] = (k < ke) ? W[(size_t)c * ldw + k] : 0.f;
        }
        __syncthreads();
        #pragma unroll
        for (int kk = 0; kk < 16; kk++) {
            ulonglong2 a01 = *(const ulonglong2*)&sm.As[kk][8*tr];
            ulonglong2 a23 = *(const ulonglong2*)&sm.As[kk][8*tr + 4];
            float4 wv = *(const float4*)&sm.Ws[kk][4*tc];
            ull ap[4] = {a01.x, a01.y, a23.x, a23.y};
            ull w2[4] = {pk2(wv.x, wv.x), pk2(wv.y, wv.y), pk2(wv.z, wv.z), pk2(wv.w, wv.w)};
            #pragma unroll
            for (int p = 0; p < 4; p++)
                #pragma unroll
                for (int j = 0; j < 4; j++)
                    acc[p][j] = ffma2(ap[p], w2[j], acc[p][j]);
        }
        __syncthreads();
    }
}

__device__ __forceinline__ void split_reduce_store(
    SplitSmem& sm, ull (&acc)[4][4], int grp, int t,
    const float* __restrict__ bias, float* __restrict__ outbase, int row0)
{
    int tc = t & 15, tr = t >> 4;
    if (grp == 1) {
        #pragma unroll
        for (int p = 0; p < 4; p++) {
            float lo[4], hi[4];
            #pragma unroll
            for (int j = 0; j < 4; j++) upk2(acc[p][j], lo[j], hi[j]);
            int r = 8*tr + 2*p;
            *(float4*)&sm.part[r][4*tc]   = make_float4(lo[0], lo[1], lo[2], lo[3]);
            *(float4*)&sm.part[r+1][4*tc] = make_float4(hi[0], hi[1], hi[2], hi[3]);
        }
    }
    __syncthreads();
    if (grp == 0) {
        float4 bv = *(const float4*)&bias[4*tc];
        #pragma unroll
        for (int p = 0; p < 4; p++) {
            float lo[4], hi[4];
            #pragma unroll
            for (int j = 0; j < 4; j++) upk2(acc[p][j], lo[j], hi[j]);
            int r = 8*tr + 2*p;
            float4 p0 = *(const float4*)&sm.part[r][4*tc];
            float4 p1 = *(const float4*)&sm.part[r+1][4*tc];
            float4 v0 = {lo[0]+p0.x+bv.x, lo[1]+p0.y+bv.y, lo[2]+p0.z+bv.z, lo[3]+p0.w+bv.w};
            float4 v1 = {hi[0]+p1.x+bv.x, hi[1]+p1.y+bv.y, hi[2]+p1.z+bv.z, hi[3]+p1.w+bv.w};
            *(float4*)&outbase[(size_t)(row0 + r)*E + 4*tc] = v0;
            *(float4*)&outbase[(size_t)(row0 + r + 1)*E + 4*tc] = v1;
        }
    }
}

// ---- blocks 0..15: M/cb; blocks 16..23: N/cb1; blocks 24..279: proj ----
__global__ __launch_bounds__(256) void combine_proj_kernel(
    const float* __restrict__ x,
    const float* __restrict__ pw, const float* __restrict__ pb,
    const float* __restrict__ fw, const float* __restrict__ fb,
    const float* __restrict__ low, const float* __restrict__ lob,
    const float* __restrict__ gow, const float* __restrict__ gob,
    const float* __restrict__ w1, const float* __restrict__ b1)
{
    __shared__ SplitSmem sm;
    int tid = threadIdx.x;
    int blk = blockIdx.x;
    if (blk < 16) {
        int idx = blk * 256 + tid;             // 0..4095
        int e = idx >> 6, f = idx & 63;
        float a = 0.f, b = 0.f;
        #pragma unroll 4
        for (int g = 0; g < E; g++) {
            a = fmaf(fw[e*2*E + g],     low[g*E + f], a);
            b = fmaf(fw[e*2*E + E + g], gow[g*E + f], b);
        }
        g_M[0][idx] = a;
        g_M[1][idx] = b;
        if (idx < E) {
            float c = fb[idx];
            for (int g = 0; g < E; g++) {
                c = fmaf(fw[idx*2*E + g], lob[g], c);
                c = fmaf(fw[idx*2*E + E + g], gob[g], c);
            }
            g_cb[idx] = c;
        }
        return;
    }
    if (blk < 24) {
        __shared__ float t0[4][64], t1[4][64];
        int c0 = (blk - 16) * 4;
        int ci = tid >> 6, g = tid & 63;
        {
            float a = 0.f, b = 0.f;
            #pragma unroll 4
            for (int e = 0; e < E; e++) {
                float wv = w1[(c0+ci)*E + e];
                a = fmaf(wv, fw[e*2*E + g], a);
                b = fmaf(wv, fw[e*2*E + E + g], b);
            }
            t0[ci][g] = a;
            t1[ci][g] = b;
        }
        __syncthreads();
        {
            int f = g;
            float a = 0.f, b = 0.f;
            #pragma unroll 4
            for (int gg = 0; gg < E; gg++) {
                a = fmaf(t0[ci][gg], low[gg*E + f], a);
                b = fmaf(t1[ci][gg], gow[gg*E + f], b);
            }
            g_N[0][(c0+ci)*E + f] = a;
            g_N[1][(c0+ci)*E + f] = b;
        }
        if (tid < 4) {
            int c = c0 + tid;
            float s = b1[c];
            for (int e = 0; e < E; e++) s = fmaf(w1[c*E + e], fb[e], s);
            for (int gg = 0; gg < E; gg++) {
                s = fmaf(t0[tid][gg], lob[gg], s);
                s = fmaf(t1[tid][gg], gob[gg], s);
            }
            g_cb1[c] = s;
        }
        return;
    }
    int row0 = (blk - 24) * 64;
    int grp = tid >> 7, t = tid & 127;
    int kb = grp ? 160 : 0;
    int ke = grp ? IN_DIM : 160;
    ull acc[4][4] = {};
    gemm64_grp(sm.h[grp], x, IN_DIM, row0, pw, IN_DIM, kb, ke, 10, acc, t);
    split_reduce_store(sm, acc, grp, t, pb, g_xp, row0);
}

// ---------------- QKV: 64 rows x 192 cols per block, 256 threads ----------------
__global__ __launch_bounds__(256) void qkv_kernel(const float* __restrict__ loc_w,
                           const float* __restrict__ loc_b,
                           const float* __restrict__ glb_w,
                           const float* __restrict__ glb_b) {
    __shared__ float As[16][68];
    __shared__ float Ws[16][196];
    int tid = threadIdx.x;
    int row0 = blockIdx.x * 64;
    int attn = blockIdx.y;
    const float* w    = attn ? glb_w : loc_w;
    const float* bias = attn ? glb_b : loc_b;
    int tc = tid & 15, tr = tid >> 4;
    ull acc[2][12] = {};
    for (int k0 = 0; k0 < E; k0 += 16) {
        #pragma unroll
        for (int p = 0; p < 4; p++) {          // A: 64x16
            int i = tid + p * 256;
            int kk = i & 15, r = i >> 4;
            As[kk][r] = g_xp[(size_t)(row0 + r) * E + k0 + kk];
        }
        #pragma unroll
        for (int p = 0; p < 12; p++) {         // W: 192x16
            int i = tid + p * 256;
            int kk = i & 15, c = i >> 4;
            Ws[kk][c] = w[(size_t)c * E + k0 + kk];
        }
        __syncthreads();
        #pragma unroll
        for (int kk = 0; kk < 16; kk++) {
            ulonglong2 a01 = *(const ulonglong2*)&As[kk][4*tr];
            #pragma unroll
            for (int cg = 0; cg < 3; cg++) {
                float4 wv = *(const float4*)&Ws[kk][64*cg + 4*tc];
                ull w2[4] = {pk2(wv.x, wv.x), pk2(wv.y, wv.y), pk2(wv.z, wv.z), pk2(wv.w, wv.w)};
                #pragma unroll
                for (int j = 0; j < 4; j++) {
                    acc[0][cg*4+j] = ffma2(a01.x, w2[j], acc[0][cg*4+j]);
                    acc[1][cg*4+j] = ffma2(a01.y, w2[j], acc[1][cg*4+j]);
                }
            }
        }
        __syncthreads();
    }
    int c = 4*tc;
    int h = c >> 3, dd = c & 7;
    #pragma unroll
    for (int cg = 0; cg < 3; cg++) {
        float* outp = (cg == 0) ? g_q[attn] : (cg == 1) ? g_k[attn] : g_v[attn];
        float4 bv = *(const float4*)&bias[cg*64 + c];
        #pragma unroll
        for (int p = 0; p < 2; p++) {
            float lo[4], hi[4];
            #pragma unroll
            for (int j = 0; j < 4; j++) upk2(acc[p][cg*4+j], lo[j], hi[j]);
            int row = row0 + 4*tr + 2*p;
            int b0 = row >> 10, s0 = row & 1023;
            int b1i = (row+1) >> 10, s1 = (row+1) & 1023;
            float4 v0 = {lo[0]+bv.x, lo[1]+bv.y, lo[2]+bv.z, lo[3]+bv.w};
            float4 v1 = {hi[0]+bv.x, hi[1]+bv.y, hi[2]+bv.z, hi[3]+bv.w};
            *(float4*)&outp[(((size_t)(b0*NH + h))*SEQ + s0)*HD + dd] = v0;
            *(float4*)&outp[(((size_t)(b1i*NH + h))*SEQ + s1)*HD + dd] = v1;
        }
    }
}

// ---------------- both attentions in one launch ----------------
__global__ __launch_bounds__(256) void attn_kernel() {
    __shared__ union {
        struct { float Ks[NKEYS][8]; float Vs[NKEYS][8]; } sp;
        struct { ull K2[4][272]; ull V2[4][272]; } loc;
    } u;
    int blk = blockIdx.x;
    int tid = threadIdx.x;
    if (blk < 512) {
        int bh = blk >> 2;
        int chunk0 = (blk & 3) * 256;
        const float* kb = g_k[0] + (size_t)bh * SEQ * HD;
        const float* vb = g_v[0] + (size_t)bh * SEQ * HD;
        for (int i = tid; i < 266*4; i += 256) {
            int dp = i & 3, r = i >> 2;
            int row = chunk0 - 5 + r;
            ull kv = 0, vv = 0;
            if (row >= 0 && row < SEQ) {
                kv = *(const ull*)(kb + (size_t)row*HD + 2*dp);
                vv = *(const ull*)(vb + (size_t)row*HD + 2*dp);
            }
            u.loc.K2[dp][r] = kv;
            u.loc.V2[dp][r] = vv;
        }
        __syncthreads();
        int s = chunk0 + tid;
        const ull* qp = (const ull*)(g_q[0] + ((size_t)bh * SEQ + s) * HD);
        ull q0 = qp[0], q1 = qp[1], q2 = qp[2], q3 = qp[3];
        float l = 0.f;
        ull acc[4] = {0,0,0,0};
        int j0 = s - WIN;
        #pragma unroll
        for (int jj = 0; jj < 2*WIN+1; jj++) {
            int r = tid + jj;
            ull d2 = ffma2(q0, u.loc.K2[0][r],
                     ffma2(q1, u.loc.K2[1][r],
                     ffma2(q2, u.loc.K2[2][r],
                     fmul2(q3, u.loc.K2[3][r]))));
            float dl, dh; upk2(d2, dl, dh);
            unsigned jg = (unsigned)(j0 + jj);
            float p = (jg < SEQ) ? __expf((dl + dh) * SCALE) : 0.f;
            l += p;
            ull pp = pk2(p, p);
            acc[0] = ffma2(pp, u.loc.V2[0][r], acc[0]);
            acc[1] = ffma2(pp, u.loc.V2[1][r], acc[1]);
            acc[2] = ffma2(pp, u.loc.V2[2][r], acc[2]);
            acc[3] = ffma2(pp, u.loc.V2[3][r], acc[3]);
        }
        float inv = 1.f / l;
        float oo[8];
        upk2(acc[0], oo[0], oo[1]); upk2(acc[1], oo[2], oo[3]);
        upk2(acc[2], oo[4], oo[5]); upk2(acc[3], oo[6], oo[7]);
        int b = bh >> 3, h = bh & 7;
        float* op = g_o[0] + ((size_t)(b*SEQ + s))*E + h*HD;
        float4 o0 = {oo[0]*inv, oo[1]*inv, oo[2]*inv, oo[3]*inv};
        float4 o1 = {oo[4]*inv, oo[5]*inv, oo[6]*inv, oo[7]*inv};
        *(float4*)op = o0;
        *(float4*)(op + 4) = o1;
    } else {
        int bb = blk - 512;
        int bh = bb >> 2;
        int s  = (bb & 3) * 256 + tid;
        const float* kb = g_k[1] + (size_t)bh * SEQ * HD;
        const float* vb = g_v[1] + (size_t)bh * SEQ * HD;
        for (int i = tid; i < NKEYS*8; i += 256) {
            int kk = i >> 3, dd = i & 7;
            u.sp.Ks[kk][dd] = kb[kk*24 + dd];
            u.sp.Vs[kk][dd] = vb[kk*24 + dd];
        }
        __syncthreads();
        const ull* qp = (const ull*)(g_q[1] + ((size_t)bh * SEQ + s) * HD);
        ull q0 = qp[0], q1 = qp[1], q2 = qp[2], q3 = qp[3];
        float l = 0.f;
        ull acc[4] = {0,0,0,0};
        #pragma unroll 2
        for (int kk = 0; kk < NKEYS; kk++) {
            const ull* kp = (const ull*)&u.sp.Ks[kk][0];
            ull d2 = ffma2(q0, kp[0], ffma2(q1, kp[1], ffma2(q2, kp[2], fmul2(q3, kp[3]))));
            float dl, dh; upk2(d2, dl, dh);
            float p = __expf((dl + dh) * SCALE);
            l += p;
            ull pp = pk2(p, p);
            const ull* vp = (const ull*)&u.sp.Vs[kk][0];
            acc[0] = ffma2(pp, vp[0], acc[0]);
            acc[1] = ffma2(pp, vp[1], acc[1]);
            acc[2] = ffma2(pp, vp[2], acc[2]);
            acc[3] = ffma2(pp, vp[3], acc[3]);
        }
        if (s % 3) {
            const ull* kp = (const ull*)(kb + (size_t)s * HD);
            ull d2 = ffma2(q0, kp[0], ffma2(q1, kp[1], ffma2(q2, kp[2], fmul2(q3, kp[3]))));
            float dl, dh; upk2(d2, dl, dh);
            float p = __expf((dl + dh) * SCALE);
            l += p;
            ull pp = pk2(p, p);
            const ull* vp = (const ull*)(vb + (size_t)s * HD);
            acc[0] = ffma2(pp, vp[0], acc[0]);
            acc[1] = ffma2(pp, vp[1], acc[1]);
            acc[2] = ffma2(pp, vp[2], acc[2]);
            acc[3] = ffma2(pp, vp[3], acc[3]);
        }
        float inv = 1.f / l;
        float oo[8];
        upk2(acc[0], oo[0], oo[1]); upk2(acc[1], oo[2], oo[3]);
        upk2(acc[2], oo[4], oo[5]); upk2(acc[3], oo[6], oo[7]);
        int b = bh >> 3, h = bh & 7;
        float* op = g_o[1] + ((size_t)(b*SEQ + s))*E + h*HD;
        float4 o0 = {oo[0]*inv, oo[1]*inv, oo[2]*inv, oo[3]*inv};
        float4 o1 = {oo[4]*inv, oo[5]*inv, oo[6]*inv, oo[7]*inv};
        *(float4*)op = o0;
        *(float4*)(op + 4) = o1;
    }
}

// ---------------- score_pool: scores + pooled partials, one o-read ----------------
// grid 512: one block per 32 rows. o tiles staged TRANSPOSED in smem and reused
// for both the score GEMM and the weighted pooling sum.
struct ScorePoolSmem {
    float At[2][64][36];    // [grp][k][row] transposed o tiles
    float Wc[2][64][36];    // [grp][k][col] N matrices (col 0..31)
    float part[32][36];     // hidden pre-tanh
    float wexp[32];         // exp(score)
    float p0[4][64], p1[4][64];
    float esum_s;
};

__global__ __launch_bounds__(256) void score_pool_kernel(
    const float* __restrict__ w2, const float* __restrict__ b2)
{
    __shared__ __align__(16) ScorePoolSmem sm;
    int tid = threadIdx.x;
    int row0 = blockIdx.x * 32;
    int b = row0 >> 10, ch = (row0 & 1023) >> 5;
    int grp = tid >> 7, t = tid & 127;
    const float* A = grp ? g_o[1] : g_o[0];
    const float* W = grp ? g_N[1] : g_N[0];
    // stage o tile transposed: At[k][r] = A[(row0+r)*E + k]
    #pragma unroll
    for (int p = 0; p < 4; p++) {
        int i = t + p * 128;          // 0..511
        int r = i >> 4, k4 = (i & 15) * 4;
        float4 v = *(const float4*)&A[(size_t)(row0 + r) * E + k4];
        sm.At[grp][k4+0][r] = v.x;
        sm.At[grp][k4+1][r] = v.y;
        sm.At[grp][k4+2][r] = v.z;
        sm.At[grp][k4+3][r] = v.w;
    }
    // stage N: Wc[k][c] = N[c*E + k]
    #pragma unroll
    for (int p = 0; p < 4; p++) {
        int i = t + p * 128;          // 0..511
        int c = i >> 4, k4 = (i & 15) * 4;
        float4 v = *(const float4*)&W[(size_t)c * E + k4];
        sm.Wc[grp][k4+0][c] = v.x;
        sm.Wc[grp][k4+1][c] = v.y;
        sm.Wc[grp][k4+2][c] = v.z;
        sm.Wc[grp][k4+3][c] = v.w;
    }
    __syncthreads();
    // score GEMM: 32 rows x 32 cols per group; thread = 4 rows x 2 cols
    int tr = t & 7, tc = t >> 3;      // tr: row group (4 rows), tc: col pair
    ull acc[2][2] = {};
    #pragma unroll
    for (int kk = 0; kk < 64; kk++) {
        ulonglong2 a = *(const ulonglong2*)&sm.At[grp][kk][4*tr];
        float2 wv = *(const float2*)&sm.Wc[grp][kk][2*tc];
        ull w0 = pk2(wv.x, wv.x), w1 = pk2(wv.y, wv.y);
        acc[0][0] = ffma2(a.x, w0, acc[0][0]);
        acc[0][1] = ffma2(a.x, w1, acc[0][1]);
        acc[1][0] = ffma2(a.y, w0, acc[1][0]);
        acc[1][1] = ffma2(a.y, w1, acc[1][1]);
    }
    // cross-group reduce into part
    if (grp == 1) {
        #pragma unroll
        for (int p = 0; p < 2; p++)
            #pragma unroll
            for (int j = 0; j < 2; j++) {
                float lo, hi; upk2(acc[p][j], lo, hi);
                sm.part[4*tr + 2*p][2*tc + j]     = lo;
                sm.part[4*tr + 2*p + 1][2*tc + j] = hi;
            }
    }
    __syncthreads();
    if (grp == 0) {
        #pragma unroll
        for (int p = 0; p < 2; p++)
            #pragma unroll
            for (int j = 0; j < 2; j++) {
                float lo, hi; upk2(acc[p][j], lo, hi);
                sm.part[4*tr + 2*p][2*tc + j]     += lo;
                sm.part[4*tr + 2*p + 1][2*tc + j] += hi;
            }
    }
    __syncthreads();
    // tanh + w2 dot: thread (r = tid>>3, q = tid&7) handles 4 cols, reduce over q
    {
        int r = tid >> 3, q = tid & 7;
        float s = 0.f;
        #pragma unroll
        for (int c = q*4; c < q*4 + 4; c++) {
            float h = tanhf(sm.part[r][c] + g_cb1[c]);
            s = fmaf(h, w2[c], s);
        }
        s += __shfl_xor_sync(0xffffffffu, s, 4);
        s += __shfl_xor_sync(0xffffffffu, s, 2);
        s += __shfl_xor_sync(0xffffffffu, s, 1);
        if (q == 0) sm.wexp[r] = __expf(s + b2[0]);   // bounded scores: maxless exp exact
    }
    __syncthreads();
    // chunk exp-sum
    if (tid < 32) {
        float e = sm.wexp[tid];
        #pragma unroll
        for (int off = 16; off; off >>= 1) e += __shfl_xor_sync(0xffffffffu, e, off);
        if (tid == 0) sm.esum_s = e;
    }
    // weighted pooling from the smem-resident transposed tiles
    {
        int e = tid & 63, g = tid >> 6;
        float a0 = 0.f, a1 = 0.f;
        #pragma unroll
        for (int r = g*8; r < g*8 + 8; r++) {
            float wv = sm.wexp[r];
            a0 = fmaf(wv, sm.At[0][e][r], a0);
            a1 = fmaf(wv, sm.At[1][e][r], a1);
        }
        sm.p0[g][e] = a0;
        sm.p1[g][e] = a1;
    }
    __syncthreads();
    if (tid < 64) {
        g_part[0][b][ch][tid] = sm.p0[0][tid] + sm.p0[1][tid] + sm.p0[2][tid] + sm.p0[3][tid];
        g_part[1][b][ch][tid] = sm.p1[0][tid] + sm.p1[1][tid] + sm.p1[2][tid] + sm.p1[3][tid];
    }
    if (tid == 0) g_esum[b][ch] = sm.esum_s;
}

// ---------------- pool_final: combine partials + tiny M epilogue ----------------
__global__ void pool_final_kernel(float* __restrict__ out) {
    __shared__ float pl0[64], pl1[64];
    int b = blockIdx.x;
    int tid = threadIdx.x;   // 64
    float es = 0.f;
    #pragma unroll
    for (int c = 0; c < 32; c++) es += g_esum[b][c];
    float inv = 1.f / es;
    float s0 = 0.f, s1 = 0.f;
    #pragma unroll
    for (int c = 0; c < 32; c++) {
        s0 += g_part[0][b][c][tid];
        s1 += g_part[1][b][c][tid];
    }
    pl0[tid] = s0 * inv;
    pl1[tid] = s1 * inv;
    __syncthreads();
    float s = g_cb[tid];
    const float* m0 = &g_M[0][tid*E];
    const float* m1 = &g_M[1][tid*E];
    #pragma unroll 4
    for (int f = 0; f < E; f++) {
        s = fmaf(pl0[f], m0[f], s);
        s = fmaf(pl1[f], m1[f], s);
    }
    out[b*E + tid] = s;
}

// ---------------- launch ----------------
extern "C" void kernel_launch(void* const* d_in, const int* in_sizes, int n_in,
                              void* d_out, int out_size) {
    const float* x        = (const float*)d_in[0];
    const float* proj_w   = (const float*)d_in[1];
    const float* proj_b   = (const float*)d_in[2];
    const float* loc_in_w = (const float*)d_in[3];
    const float* loc_in_b = (const float*)d_in[4];
    const float* loc_out_w= (const float*)d_in[5];
    const float* loc_out_b= (const float*)d_in[6];
    const float* glb_in_w = (const float*)d_in[7];
    const float* glb_in_b = (const float*)d_in[8];
    const float* glb_out_w= (const float*)d_in[9];
    const float* glb_out_b= (const float*)d_in[10];
    const float* fusion_w = (const float*)d_in[11];
    const float* fusion_b = (const float*)d_in[12];
    const float* pool_w1  = (const float*)d_in[13];
    const float* pool_b1  = (const float*)d_in[14];
    const float* pool_w2  = (const float*)d_in[15];
    const float* pool_b2  = (const float*)d_in[16];
    float* out = (float*)d_out;

    combine_proj_kernel<<<24 + ROWS/64, 256>>>(x, proj_w, proj_b,
                                               fusion_w, fusion_b,
                                               loc_out_w, loc_out_b,
                                               glb_out_w, glb_out_b,
                                               pool_w1, pool_b1);
    qkv_kernel<<<dim3(ROWS/64, 2), 256>>>(loc_in_w, loc_in_b, glb_in_w, glb_in_b);
    attn_kernel<<<1024, 256>>>();
    score_pool_kernel<<<ROWS/32, 256>>>(pool_w2, pool_b2);
    pool_final_kernel<<<BATCH, 64>>>(out);
}